// round 9
// baseline (speedup 1.0000x reference)
#include <cuda_runtime.h>
#include <cuda_bf16.h>
#include <cstdint>

// Problem constants
#define B_   32
#define C_   64
#define HW_  1024
#define N_   32768          // B*H*W
#define K_   1024
#define TMZ  128            // points per prep block
#define TMV  64             // points per vq block tile
#define NT   128            // codes per vq block tile (one slice)

// ---------------------------------------------------------------------------
// Scratch (no cudaMalloc allowed)
// ---------------------------------------------------------------------------
__device__ unsigned short g_x1[N_ * C_];      // bf16 round of z, row-major [n][c]
__device__ float          g_xrm[N_ * C_];     // fp32 z, row-major [n][c]
__device__ unsigned short g_c1[K_ * C_];      // bf16 round of cb, [k][c]
__device__ float g_hn[K_];                    // 0.5*||c_k||^2
__device__ float g_xS[N_];                    // sum_i |x_i| per point
__device__ unsigned long long g_best[N_];     // packed (monotone dist | idx)

// Monotone float->uint mapping (preserves total order incl. negatives)
__device__ __forceinline__ unsigned int fkey(float f) {
    unsigned int u = __float_as_uint(f);
    return (u & 0x80000000u) ? ~u : (u | 0x80000000u);
}

__device__ __forceinline__ unsigned int smem_u32(const void* p) {
    unsigned int a;
    asm("{ .reg .u64 t; cvta.to.shared.u64 t, %1; cvt.u32.u64 %0, t; }"
        : "=r"(a) : "l"(p));
    return a;
}

// ---------------------------------------------------------------------------
// Prep z: bf16 round + fp32 row-major copy + sum|x| + g_best init.
// 256 blocks x 256 threads (one block = 128 points).
// ---------------------------------------------------------------------------
__global__ __launch_bounds__(256)
void prep_z_kernel(const float* __restrict__ z) {
    __shared__ float xs[C_ * TMZ];     // [c][m]
    const int tid = threadIdx.x;
    const int n0  = blockIdx.x * TMZ;
    const int b   = n0 / HW_;
    const int hw0 = n0 % HW_;
    const float* zb = z + (size_t)b * C_ * HW_ + hw0;

    {
        int m4 = (tid & 31) * 4;
        int c0 = tid >> 5;
#pragma unroll
        for (int cc = 0; cc < 8; ++cc) {
            int c = c0 + cc * 8;
            *(float4*)&xs[c * TMZ + m4] = *(const float4*)&zb[c * HW_ + m4];
        }
    }
    __syncthreads();

    if (tid < TMZ) {
        const int m = tid;
        const int n = n0 + m;
        const size_t nrow = (size_t)n * C_;
        float S = 0.f;
#pragma unroll
        for (int c0 = 0; c0 < C_; c0 += 8) {
            uint4 p1;
            unsigned short* s1 = (unsigned short*)&p1;
            float xv[8];
#pragma unroll
            for (int j = 0; j < 8; ++j) {
                float x = xs[(c0 + j) * TMZ + m];
                xv[j] = x;
                S += fabsf(x);
                s1[j] = __bfloat16_as_ushort(__float2bfloat16(x));
            }
            *(uint4*)&g_x1[nrow + c0] = p1;
            *(float4*)&g_xrm[nrow + c0]     = make_float4(xv[0], xv[1], xv[2], xv[3]);
            *(float4*)&g_xrm[nrow + c0 + 4] = make_float4(xv[4], xv[5], xv[6], xv[7]);
        }
        g_xS[n]   = S;
        g_best[n] = 0xFFFFFFFFFFFFFFFFull;
    }
}

// ---------------------------------------------------------------------------
// Prep codebook: bf16 round + half norms. 8 blocks x 128 threads.
// ---------------------------------------------------------------------------
__global__ __launch_bounds__(128)
void prep_cb_kernel(const float* __restrict__ cb) {
    int k = blockIdx.x * 128 + threadIdx.x;          // 0..1023
    const size_t krow = (size_t)k * C_;
    float s = 0.f;
#pragma unroll
    for (int c0 = 0; c0 < C_; c0 += 8) {
        float4 va = *(const float4*)&cb[krow + c0];
        float4 vb = *(const float4*)&cb[krow + c0 + 4];
        float xv[8] = {va.x, va.y, va.z, va.w, vb.x, vb.y, vb.z, vb.w};
        uint4 p1;
        unsigned short* s1 = (unsigned short*)&p1;
#pragma unroll
        for (int j = 0; j < 8; ++j) {
            float x = xv[j];
            s += x * x;
            s1[j] = __bfloat16_as_ushort(__float2bfloat16(x));
        }
        *(uint4*)&g_c1[krow + c0] = p1;
    }
    g_hn[k] = 0.5f * s;
}

// ---------------------------------------------------------------------------
// Main: one block = 64 points x 128 codes (one slice). bf16 MMA filter with
// rigorous margin; exact fp32 verify reads rows straight from L2.
// 4096 blocks x 256 threads (8 warps), 3 CTAs/SM.
// ---------------------------------------------------------------------------
#define SA_OFF   0            // bf16 A tile (64 rows x 128B), swizzled: 8192
#define SB_OFF   8192         // bf16 B tile (128 rows x 128B), swizzled: 16384
#define SHN_OFF  24576        // hn slice: 512
#define SXS_OFF  25088        // sum|x|: 256
#define SQC_OFF  25344        // queue count: 16
#define SQ_OFF   25360        // queue: QCAP * 4
#define QCAP     1536
#define SMEM_SZ  (25360 + QCAP * 4)

__global__ __launch_bounds__(256, 3)
void vq_kernel(const float* __restrict__ cb) {
    extern __shared__ char smem[];
    const unsigned int sbase = smem_u32(smem);
    float* shn = (float*)(smem + SHN_OFF);
    float* sxs = (float*)(smem + SXS_OFF);
    int*   qc  = (int*)(smem + SQC_OFF);
    int*   qu  = (int*)(smem + SQ_OFF);

    const int tid  = threadIdx.x;
    const int wid  = tid >> 5;
    const int lane = tid & 31;
    const int tile = blockIdx.x >> 3;          // 0..511 point tile (64 points)
    const int ks   = blockIdx.x & 7;           // 0..7 code slice
    const int n0   = tile * TMV;

    // ---- stage bf16 tiles (swizzled), hn, sum|x| ----
    {
        const uint4* srcA = (const uint4*)(g_x1 + (size_t)n0 * C_);
        const uint4* srcB = (const uint4*)(g_c1 + (size_t)ks * NT * C_);
#pragma unroll
        for (int i = 0; i < 2; ++i) {
            int idx = tid + i * 256;           // 0..511
            int row = idx >> 3;
            int chk = idx & 7;
            int sw  = row * 128 + ((chk ^ (row & 7)) * 16);
            *(uint4*)(smem + SA_OFF + sw) = srcA[idx];
        }
#pragma unroll
        for (int i = 0; i < 4; ++i) {
            int idx = tid + i * 256;           // 0..1023
            int row = idx >> 3;
            int chk = idx & 7;
            int sw  = row * 128 + ((chk ^ (row & 7)) * 16);
            *(uint4*)(smem + SB_OFF + sw) = srcB[idx];
        }
        if (tid < NT)  shn[tid] = g_hn[ks * NT + tid];
        if (tid < TMV) sxs[tid] = g_xS[n0 + tid];
        if (tid == 0) *qc = 0;
    }
    __syncthreads();

    // ---- warp tiling: 8 warps = 4 M-groups (16 rows) x 2 N-halves (64) ----
    const int mrow0 = (wid & 3) * 16;
    const int ncol0 = (wid >> 2) * 64;
    const int q  = lane >> 3;
    const int rl = lane & 7;
    const int arow = (q & 1) * 8 + rl;
    const int akhalf = q >> 1;
    const int brow = (q >> 1) * 8 + rl;
    const int bkhalf = q & 1;

    float acc[8][4];
#pragma unroll
    for (int nt = 0; nt < 8; ++nt)
#pragma unroll
        for (int e = 0; e < 4; ++e) acc[nt][e] = 0.f;

#pragma unroll
    for (int kc = 0; kc < 4; ++kc) {
        unsigned int af[4];
        {
            int row = mrow0 + arow;
            unsigned int addr = sbase + SA_OFF + row * 128
                              + (((kc * 2 + akhalf) ^ rl) * 16);
            asm volatile("ldmatrix.sync.aligned.m8n8.x4.shared.b16 "
                         "{%0,%1,%2,%3}, [%4];"
                         : "=r"(af[0]), "=r"(af[1]), "=r"(af[2]), "=r"(af[3])
                         : "r"(addr));
        }
        unsigned int bf[4][4];
#pragma unroll
        for (int nt2 = 0; nt2 < 4; ++nt2) {
            int row = ncol0 + nt2 * 16 + brow;
            unsigned int addr = sbase + SB_OFF + row * 128
                              + (((kc * 2 + bkhalf) ^ rl) * 16);
            asm volatile("ldmatrix.sync.aligned.m8n8.x4.shared.b16 "
                         "{%0,%1,%2,%3}, [%4];"
                         : "=r"(bf[nt2][0]), "=r"(bf[nt2][1]),
                           "=r"(bf[nt2][2]), "=r"(bf[nt2][3])
                         : "r"(addr));
        }
#pragma unroll
        for (int nt = 0; nt < 8; ++nt) {
            int nt2 = nt >> 1, hi = nt & 1;
            asm volatile(
                "mma.sync.aligned.m16n8k16.row.col.f32.bf16.bf16.f32 "
                "{%0,%1,%2,%3}, {%4,%5,%6,%7}, {%8,%9}, {%0,%1,%2,%3};"
                : "+f"(acc[nt][0]), "+f"(acc[nt][1]),
                  "+f"(acc[nt][2]), "+f"(acc[nt][3])
                : "r"(af[0]), "r"(af[1]), "r"(af[2]), "r"(af[3]),
                  "r"(bf[nt2][hi * 2]), "r"(bf[nt2][hi * 2 + 1]));
        }
    }

    // ---- approx per-row min over this warp's 64 cols ----
    float bv[2] = {3.4e38f, 3.4e38f};          // rows lane>>2 and lane>>2 + 8
#pragma unroll
    for (int nt = 0; nt < 8; ++nt) {
        int colb = ncol0 + nt * 8 + (lane & 3) * 2;
        float h0 = shn[colb], h1 = shn[colb + 1];
#pragma unroll
        for (int h = 0; h < 2; ++h) {
            float s0 = h0 - acc[nt][h * 2 + 0];
            float s1 = h1 - acc[nt][h * 2 + 1];
            bv[h] = fminf(bv[h], fminf(s0, s1));
        }
    }
#pragma unroll
    for (int h = 0; h < 2; ++h) {
#pragma unroll
        for (int off = 1; off <= 2; off <<= 1)
            bv[h] = fminf(bv[h], __shfl_xor_sync(0xffffffffu, bv[h], off));
    }

    // ---- rigorous margin threshold; queue candidates ----
    // |exact - approx| <= 2*2^-8*1.004*S + slack  (|c_i| < 1, bf16 u=2^-8)
    float T[2];
#pragma unroll
    for (int h = 0; h < 2; ++h) {
        int row = mrow0 + (lane >> 2) + 8 * h;
        T[h] = bv[h] + sxs[row] * 0.0158f + 0.002f;
    }

#pragma unroll
    for (int nt = 0; nt < 8; ++nt) {
        int colb = ncol0 + nt * 8 + (lane & 3) * 2;
        float h0 = shn[colb], h1 = shn[colb + 1];
#pragma unroll
        for (int h = 0; h < 2; ++h) {
            int row = mrow0 + (lane >> 2) + 8 * h;
            float s0 = h0 - acc[nt][h * 2 + 0];
            float s1 = h1 - acc[nt][h * 2 + 1];
#pragma unroll
            for (int e = 0; e < 2; ++e) {
                float s = e ? s1 : s0;
                int col = colb + e;
                if (s <= T[h]) {
                    int idx = atomicAdd(qc, 1);
                    if (idx < QCAP) {
                        qu[idx] = (row << 8) | col;
                    } else {
                        // overflow fallback: inline exact eval from L2
                        const float* xr = &g_xrm[(size_t)(n0 + row) * C_];
                        const float* cr = &cb[(size_t)(ks * NT + col) * C_];
                        float sx = shn[col];
#pragma unroll 8
                        for (int c = 0; c < C_; ++c)
                            sx = fmaf(-xr[c], cr[c], sx);
                        unsigned long long key =
                            ((unsigned long long)fkey(sx) << 32)
                            | (unsigned int)(ks * NT + col);
                        atomicMin(&g_best[n0 + row], key);
                    }
                }
            }
        }
    }
    __syncthreads();

    // ---- exact fp32 verification of queued candidates (rows from L2) ----
    int qn = *qc;
    if (qn > QCAP) qn = QCAP;
    for (int i = tid; i < qn; i += 256) {
        int e   = qu[i];
        int row = e >> 8;
        int col = e & 255;
        const float4* xr = (const float4*)&g_xrm[(size_t)(n0 + row) * C_];
        const float4* cr = (const float4*)&cb[(size_t)(ks * NT + col) * C_];
        float s = shn[col];
#pragma unroll
        for (int c = 0; c < 16; ++c) {
            float4 xv = xr[c];
            float4 cv = cr[c];
            s = fmaf(-xv.x, cv.x, s);
            s = fmaf(-xv.y, cv.y, s);
            s = fmaf(-xv.z, cv.z, s);
            s = fmaf(-xv.w, cv.w, s);
        }
        unsigned long long key =
            ((unsigned long long)fkey(s) << 32)
            | (unsigned int)(ks * NT + col);
        atomicMin(&g_best[n0 + row], key);
    }
}

// ---------------------------------------------------------------------------
// Finalize: 1024 blocks x 128 threads, 32 points each. float4 output stores.
// ---------------------------------------------------------------------------
#define TF 32
__global__ __launch_bounds__(128)
void finalize_kernel(const float* __restrict__ cb, float* __restrict__ out) {
    __shared__ float scodes[TF * 65];
    __shared__ int   sidx[TF];

    const int tid = threadIdx.x;
    const int n0  = blockIdx.x * TF;
    const int b   = n0 / HW_;
    const int hw0 = n0 % HW_;

    if (tid < TF) {
        unsigned long long key = g_best[n0 + tid];
        int idx = (int)(unsigned int)(key & 0xFFFFFFFFull);
        sidx[tid] = idx;
        out[(size_t)B_ * C_ * HW_ + n0 + tid] = (float)idx;
    }
    __syncthreads();

    // gather winning codebook rows -> smem (pad 65)
    {
#pragma unroll
        for (int i = 0; i < 4; ++i) {
            int idx = tid + i * 128;           // 0..511 float4s
            int m   = idx >> 4;
            int c4  = (idx & 15) * 4;
            float4 v = *(const float4*)&cb[sidx[m] * C_ + c4];
            scodes[m * 65 + c4 + 0] = v.x;
            scodes[m * 65 + c4 + 1] = v.y;
            scodes[m * 65 + c4 + 2] = v.z;
            scodes[m * 65 + c4 + 3] = v.w;
        }
    }
    __syncthreads();

    // coalesced [B,C,H,W] float4 writes along m
    {
        int m4    = (tid & 7) * 4;             // 0..28
        int cbase = tid >> 3;                  // 0..15
        float* ob = out + (size_t)b * C_ * HW_ + hw0;
#pragma unroll
        for (int j = 0; j < 4; ++j) {
            int c = cbase + j * 16;
            float4 w;
            w.x = scodes[(m4 + 0) * 65 + c];
            w.y = scodes[(m4 + 1) * 65 + c];
            w.z = scodes[(m4 + 2) * 65 + c];
            w.w = scodes[(m4 + 3) * 65 + c];
            *(float4*)&ob[c * HW_ + m4] = w;
        }
    }
}

// ---------------------------------------------------------------------------
extern "C" void kernel_launch(void* const* d_in, const int* in_sizes, int n_in,
                              void* d_out, int out_size) {
    const float* z  = (const float*)d_in[0];
    const float* cb = (const float*)d_in[1];
    float* out = (float*)d_out;
    (void)in_sizes; (void)n_in; (void)out_size;

    cudaFuncSetAttribute(vq_kernel,
                         cudaFuncAttributeMaxDynamicSharedMemorySize, SMEM_SZ);

    prep_z_kernel<<<256, 256>>>(z);
    prep_cb_kernel<<<8, 128>>>(cb);
    vq_kernel<<<4096, 256, SMEM_SZ>>>(cb);
    finalize_kernel<<<1024, 128>>>(cb, out);
}

// round 10
// speedup vs baseline: 1.1630x; 1.1630x over previous
#include <cuda_runtime.h>
#include <cuda_bf16.h>
#include <cstdint>

// Problem constants
#define B_   32
#define C_   64
#define HW_  1024
#define N_   32768          // B*H*W
#define K_   1024
#define TM   128            // points per block tile
#define NT   128            // codes per block tile (one slice)

// ---------------------------------------------------------------------------
// Scratch (no cudaMalloc allowed)
// ---------------------------------------------------------------------------
__device__ unsigned short g_x1[N_ * C_];      // bf16 round of z, row-major [n][c]
__device__ float          g_xrm[N_ * C_];     // fp32 z, row-major [n][c]
__device__ unsigned short g_c1[K_ * C_];      // bf16 round of cb, [k][c]
__device__ float g_hn[K_];                    // 0.5*||c_k||^2
__device__ float g_xS[N_];                    // sum_i |x_i| per point
__device__ unsigned long long g_best[N_];     // packed (monotone dist | idx)

// Monotone float->uint mapping (preserves total order incl. negatives)
__device__ __forceinline__ unsigned int fkey(float f) {
    unsigned int u = __float_as_uint(f);
    return (u & 0x80000000u) ? ~u : (u | 0x80000000u);
}

__device__ __forceinline__ unsigned int smem_u32(const void* p) {
    unsigned int a;
    asm("{ .reg .u64 t; cvta.to.shared.u64 t, %1; cvt.u32.u64 %0, t; }"
        : "=r"(a) : "l"(p));
    return a;
}

// ---------------------------------------------------------------------------
// Prep z: bf16 round + fp32 row-major copy + sum|x| + g_best init.
// 256 blocks x 256 threads (one block = 128 points).
// ---------------------------------------------------------------------------
__global__ __launch_bounds__(256)
void prep_z_kernel(const float* __restrict__ z) {
    __shared__ float xs[C_ * TM];      // [c][m]
    const int tid = threadIdx.x;
    const int n0  = blockIdx.x * TM;
    const int b   = n0 / HW_;
    const int hw0 = n0 % HW_;
    const float* zb = z + (size_t)b * C_ * HW_ + hw0;

    {
        int m4 = (tid & 31) * 4;
        int c0 = tid >> 5;
#pragma unroll
        for (int cc = 0; cc < 8; ++cc) {
            int c = c0 + cc * 8;
            *(float4*)&xs[c * TM + m4] = *(const float4*)&zb[c * HW_ + m4];
        }
    }
    __syncthreads();

    if (tid < TM) {
        const int m = tid;
        const int n = n0 + m;
        const size_t nrow = (size_t)n * C_;
        float S = 0.f;
#pragma unroll
        for (int c0 = 0; c0 < C_; c0 += 8) {
            uint4 p1;
            unsigned short* s1 = (unsigned short*)&p1;
            float xv[8];
#pragma unroll
            for (int j = 0; j < 8; ++j) {
                float x = xs[(c0 + j) * TM + m];
                xv[j] = x;
                S += fabsf(x);
                s1[j] = __bfloat16_as_ushort(__float2bfloat16(x));
            }
            *(uint4*)&g_x1[nrow + c0] = p1;
            *(float4*)&g_xrm[nrow + c0]     = make_float4(xv[0], xv[1], xv[2], xv[3]);
            *(float4*)&g_xrm[nrow + c0 + 4] = make_float4(xv[4], xv[5], xv[6], xv[7]);
        }
        g_xS[n]   = S;
        g_best[n] = 0xFFFFFFFFFFFFFFFFull;
    }
}

// ---------------------------------------------------------------------------
// Prep codebook: bf16 round + half norms. 8 blocks x 128 threads.
// ---------------------------------------------------------------------------
__global__ __launch_bounds__(128)
void prep_cb_kernel(const float* __restrict__ cb) {
    int k = blockIdx.x * 128 + threadIdx.x;          // 0..1023
    const size_t krow = (size_t)k * C_;
    float s = 0.f;
#pragma unroll
    for (int c0 = 0; c0 < C_; c0 += 8) {
        float4 va = *(const float4*)&cb[krow + c0];
        float4 vb = *(const float4*)&cb[krow + c0 + 4];
        float xv[8] = {va.x, va.y, va.z, va.w, vb.x, vb.y, vb.z, vb.w};
        uint4 p1;
        unsigned short* s1 = (unsigned short*)&p1;
#pragma unroll
        for (int j = 0; j < 8; ++j) {
            float x = xv[j];
            s += x * x;
            s1[j] = __bfloat16_as_ushort(__float2bfloat16(x));
        }
        *(uint4*)&g_c1[krow + c0] = p1;
    }
    g_hn[k] = 0.5f * s;
}

// ---------------------------------------------------------------------------
// Main: one block = 128 points x 128 codes (one slice). bf16 MMA filter,
// BALLOT-based branch-free candidate queueing, exact fp32 verify
// (x rows from smem, c rows from L2). 2048 blocks x 256 threads, occ 2.
// ---------------------------------------------------------------------------
#define XPAD     68           // fp32 x-tile row stride (floats), float4-aligned
#define SA_OFF   0            // bf16 A tile, swizzled: 16384
#define SB_OFF   16384        // bf16 B tile, swizzled: 16384
#define SXF_OFF  32768        // fp32 x [128][68]: 34816
#define SHN_OFF  67584        // hn slice: 512
#define SXS_OFF  68096        // sum|x|: 512
#define SQC_OFF  68608        // queue count: 16
#define SOVF_OFF 68624        // overflow row bitmask: 16
#define SQ_OFF   68640        // queue: QCAP * 4
#define QCAP     3072
#define SMEM_SZ  (68640 + QCAP * 4)

__global__ __launch_bounds__(256, 2)
void vq_kernel(const float* __restrict__ cb) {
    extern __shared__ char smem[];
    const unsigned int sbase = smem_u32(smem);
    float* xf  = (float*)(smem + SXF_OFF);
    float* shn = (float*)(smem + SHN_OFF);
    float* sxs = (float*)(smem + SXS_OFF);
    int*   qc  = (int*)(smem + SQC_OFF);
    unsigned int* ovf = (unsigned int*)(smem + SOVF_OFF);
    int*   qu  = (int*)(smem + SQ_OFF);

    const int tid  = threadIdx.x;
    const int wid  = tid >> 5;
    const int lane = tid & 31;
    const unsigned int ltmask = (1u << lane) - 1u;
    const int tile = blockIdx.x >> 3;          // 0..255
    const int ks   = blockIdx.x & 7;           // 0..7
    const int n0   = tile * TM;

    // ---- stage bf16 tiles (swizzled) + fp32 x tile (pad 68, float4) ----
    {
        const uint4* srcA = (const uint4*)(g_x1 + (size_t)n0 * C_);
        const uint4* srcB = (const uint4*)(g_c1 + (size_t)ks * NT * C_);
#pragma unroll
        for (int i = 0; i < 4; ++i) {
            int idx = tid + i * 256;           // 0..1023 16B chunks
            int row = idx >> 3;
            int chk = idx & 7;
            int sw  = row * 128 + ((chk ^ (row & 7)) * 16);
            *(uint4*)(smem + SA_OFF + sw) = srcA[idx];
            *(uint4*)(smem + SB_OFF + sw) = srcB[idx];
        }
        const float4* srcX = (const float4*)(g_xrm + (size_t)n0 * C_);
#pragma unroll
        for (int i = 0; i < 8; ++i) {
            int idx = tid + i * 256;           // 0..2047 float4s
            int row = idx >> 4;
            int c4  = (idx & 15) * 4;
            *(float4*)&xf[row * XPAD + c4] = srcX[idx];
        }
        if (tid < NT) {
            shn[tid] = g_hn[ks * NT + tid];
            sxs[tid] = g_xS[n0 + tid];
        }
        if (tid == 0) *qc = 0;
        if (tid < 4)  ovf[tid] = 0u;
    }
    __syncthreads();

    // ---- MMA: single bf16 product, 4 k16 chunks (filter scores) ----
    const int mrow0 = (wid & 3) * 32;
    const int ncol0 = (wid >> 2) * 64;
    const int q  = lane >> 3;
    const int rl = lane & 7;
    const int arow = (q & 1) * 8 + rl;
    const int akhalf = q >> 1;
    const int brow = (q >> 1) * 8 + rl;
    const int bkhalf = q & 1;

    float acc[2][8][4];
#pragma unroll
    for (int mt = 0; mt < 2; ++mt)
#pragma unroll
        for (int nt = 0; nt < 8; ++nt)
#pragma unroll
            for (int e = 0; e < 4; ++e) acc[mt][nt][e] = 0.f;

#pragma unroll
    for (int kc = 0; kc < 4; ++kc) {
        unsigned int af[2][4];
#pragma unroll
        for (int mt = 0; mt < 2; ++mt) {
            int row = mrow0 + mt * 16 + arow;
            unsigned int addr = sbase + SA_OFF + row * 128
                              + (((kc * 2 + akhalf) ^ rl) * 16);
            asm volatile("ldmatrix.sync.aligned.m8n8.x4.shared.b16 "
                         "{%0,%1,%2,%3}, [%4];"
                         : "=r"(af[mt][0]), "=r"(af[mt][1]),
                           "=r"(af[mt][2]), "=r"(af[mt][3])
                         : "r"(addr));
        }
        unsigned int bf[4][4];
#pragma unroll
        for (int nt2 = 0; nt2 < 4; ++nt2) {
            int row = ncol0 + nt2 * 16 + brow;
            unsigned int addr = sbase + SB_OFF + row * 128
                              + (((kc * 2 + bkhalf) ^ rl) * 16);
            asm volatile("ldmatrix.sync.aligned.m8n8.x4.shared.b16 "
                         "{%0,%1,%2,%3}, [%4];"
                         : "=r"(bf[nt2][0]), "=r"(bf[nt2][1]),
                           "=r"(bf[nt2][2]), "=r"(bf[nt2][3])
                         : "r"(addr));
        }
#pragma unroll
        for (int mt = 0; mt < 2; ++mt) {
#pragma unroll
            for (int nt = 0; nt < 8; ++nt) {
                int nt2 = nt >> 1, hi = nt & 1;
                asm volatile(
                    "mma.sync.aligned.m16n8k16.row.col.f32.bf16.bf16.f32 "
                    "{%0,%1,%2,%3}, {%4,%5,%6,%7}, {%8,%9}, {%0,%1,%2,%3};"
                    : "+f"(acc[mt][nt][0]), "+f"(acc[mt][nt][1]),
                      "+f"(acc[mt][nt][2]), "+f"(acc[mt][nt][3])
                    : "r"(af[mt][0]), "r"(af[mt][1]),
                      "r"(af[mt][2]), "r"(af[mt][3]),
                      "r"(bf[nt2][hi * 2]), "r"(bf[nt2][hi * 2 + 1]));
            }
        }
    }

    // ---- approx per-row min over this warp's 64 cols ----
    float bv[2][2];
#pragma unroll
    for (int mt = 0; mt < 2; ++mt)
#pragma unroll
        for (int h = 0; h < 2; ++h) bv[mt][h] = 3.4e38f;

#pragma unroll
    for (int nt = 0; nt < 8; ++nt) {
        int colb = ncol0 + nt * 8 + (lane & 3) * 2;
        float h0 = shn[colb], h1 = shn[colb + 1];
#pragma unroll
        for (int mt = 0; mt < 2; ++mt) {
#pragma unroll
            for (int h = 0; h < 2; ++h) {
                float s0 = h0 - acc[mt][nt][h * 2 + 0];
                float s1 = h1 - acc[mt][nt][h * 2 + 1];
                bv[mt][h] = fminf(bv[mt][h], fminf(s0, s1));
            }
        }
    }
#pragma unroll
    for (int mt = 0; mt < 2; ++mt)
#pragma unroll
        for (int h = 0; h < 2; ++h) {
#pragma unroll
            for (int off = 1; off <= 2; off <<= 1)
                bv[mt][h] = fminf(bv[mt][h],
                                  __shfl_xor_sync(0xffffffffu, bv[mt][h], off));
        }

    // ---- rigorous margin; ballot-based branch-free candidate queueing ----
    // |exact - approx| <= 2*2^-9*(1+eps)*S + accum slack; 0.0158*S is 4x safe.
    float T[2][2];
#pragma unroll
    for (int mt = 0; mt < 2; ++mt)
#pragma unroll
        for (int h = 0; h < 2; ++h) {
            int row = mrow0 + mt * 16 + (lane >> 2) + 8 * h;
            T[mt][h] = bv[mt][h] + sxs[row] * 0.0158f + 0.002f;
        }

#pragma unroll
    for (int nt = 0; nt < 8; ++nt) {
        int colb = ncol0 + nt * 8 + (lane & 3) * 2;
        float h0 = shn[colb], h1 = shn[colb + 1];
#pragma unroll
        for (int mt = 0; mt < 2; ++mt) {
#pragma unroll
            for (int h = 0; h < 2; ++h) {
                int row = mrow0 + mt * 16 + (lane >> 2) + 8 * h;
                bool p0 = (h0 - acc[mt][nt][h * 2 + 0]) <= T[mt][h];
                bool p1 = (h1 - acc[mt][nt][h * 2 + 1]) <= T[mt][h];
                unsigned int m0 = __ballot_sync(0xffffffffu, p0);
                unsigned int m1 = __ballot_sync(0xffffffffu, p1);
                if (m0 | m1) {                 // warp-uniform, rare
                    int cnt = __popc(m0) + __popc(m1);
                    int base = 0;
                    if (lane == 0) base = atomicAdd(qc, cnt);
                    base = __shfl_sync(0xffffffffu, base, 0);
                    int pos0 = base + __popc(m0 & ltmask);
                    int pos1 = base + __popc(m0) + __popc(m1 & ltmask);
                    if (p0) {
                        if (pos0 < QCAP) qu[pos0] = (row << 8) | colb;
                        else atomicOr(&ovf[row >> 5], 1u << (row & 31));
                    }
                    if (p1) {
                        if (pos1 < QCAP) qu[pos1] = (row << 8) | (colb + 1);
                        else atomicOr(&ovf[row >> 5], 1u << (row & 31));
                    }
                }
            }
        }
    }
    __syncthreads();

    // ---- exact fp32 verification: x row from smem, c row from L2 ----
    const size_t cb0 = (size_t)ks * NT * C_;
    int qn = *qc;
    if (qn > QCAP) qn = QCAP;
    for (int i = tid; i < qn; i += 256) {
        int e   = qu[i];
        int row = e >> 8;
        int col = e & 255;
        const float*  xr = &xf[row * XPAD];
        const float4* cr = (const float4*)&cb[cb0 + (size_t)col * C_];
        float s = shn[col];
#pragma unroll
        for (int c = 0; c < 16; ++c) {
            float4 cv = cr[c];
            s = fmaf(-xr[c * 4 + 0], cv.x, s);
            s = fmaf(-xr[c * 4 + 1], cv.y, s);
            s = fmaf(-xr[c * 4 + 2], cv.z, s);
            s = fmaf(-xr[c * 4 + 3], cv.w, s);
        }
        unsigned long long key =
            ((unsigned long long)fkey(s) << 32)
            | (unsigned int)(ks * NT + col);
        atomicMin(&g_best[n0 + row], key);
    }

    // ---- overflow rows (queue full): exact rescan of the whole slice ----
    if (ovf[0] | ovf[1] | ovf[2] | ovf[3]) {   // uniform, ~never taken
        for (int r = 0; r < TM; ++r) {
            if (!(ovf[r >> 5] & (1u << (r & 31)))) continue;
            if (tid < NT) {
                int col = tid;
                const float*  xr = &xf[r * XPAD];
                const float4* cr = (const float4*)&cb[cb0 + (size_t)col * C_];
                float s = shn[col];
#pragma unroll
                for (int c = 0; c < 16; ++c) {
                    float4 cv = cr[c];
                    s = fmaf(-xr[c * 4 + 0], cv.x, s);
                    s = fmaf(-xr[c * 4 + 1], cv.y, s);
                    s = fmaf(-xr[c * 4 + 2], cv.z, s);
                    s = fmaf(-xr[c * 4 + 3], cv.w, s);
                }
                unsigned long long key =
                    ((unsigned long long)fkey(s) << 32)
                    | (unsigned int)(ks * NT + col);
                atomicMin(&g_best[n0 + r], key);
            }
        }
    }
}

// ---------------------------------------------------------------------------
// Finalize: 1024 blocks x 128 threads, 32 points each. float4 output stores.
// ---------------------------------------------------------------------------
#define TF 32
__global__ __launch_bounds__(128)
void finalize_kernel(const float* __restrict__ cb, float* __restrict__ out) {
    __shared__ float scodes[TF * 65];
    __shared__ int   sidx[TF];

    const int tid = threadIdx.x;
    const int n0  = blockIdx.x * TF;
    const int b   = n0 / HW_;
    const int hw0 = n0 % HW_;

    if (tid < TF) {
        unsigned long long key = g_best[n0 + tid];
        int idx = (int)(unsigned int)(key & 0xFFFFFFFFull);
        sidx[tid] = idx;
        out[(size_t)B_ * C_ * HW_ + n0 + tid] = (float)idx;
    }
    __syncthreads();

    {
#pragma unroll
        for (int i = 0; i < 4; ++i) {
            int idx = tid + i * 128;           // 0..511 float4s
            int m   = idx >> 4;
            int c4  = (idx & 15) * 4;
            float4 v = *(const float4*)&cb[sidx[m] * C_ + c4];
            scodes[m * 65 + c4 + 0] = v.x;
            scodes[m * 65 + c4 + 1] = v.y;
            scodes[m * 65 + c4 + 2] = v.z;
            scodes[m * 65 + c4 + 3] = v.w;
        }
    }
    __syncthreads();

    {
        int m4    = (tid & 7) * 4;             // 0..28
        int cbase = tid >> 3;                  // 0..15
        float* ob = out + (size_t)b * C_ * HW_ + hw0;
#pragma unroll
        for (int j = 0; j < 4; ++j) {
            int c = cbase + j * 16;
            float4 w;
            w.x = scodes[(m4 + 0) * 65 + c];
            w.y = scodes[(m4 + 1) * 65 + c];
            w.z = scodes[(m4 + 2) * 65 + c];
            w.w = scodes[(m4 + 3) * 65 + c];
            *(float4*)&ob[c * HW_ + m4] = w;
        }
    }
}

// ---------------------------------------------------------------------------
extern "C" void kernel_launch(void* const* d_in, const int* in_sizes, int n_in,
                              void* d_out, int out_size) {
    const float* z  = (const float*)d_in[0];
    const float* cb = (const float*)d_in[1];
    float* out = (float*)d_out;
    (void)in_sizes; (void)n_in; (void)out_size;

    cudaFuncSetAttribute(vq_kernel,
                         cudaFuncAttributeMaxDynamicSharedMemorySize, SMEM_SZ);

    prep_z_kernel<<<256, 256>>>(z);
    prep_cb_kernel<<<8, 128>>>(cb);
    vq_kernel<<<2048, 256, SMEM_SZ>>>(cb);
    finalize_kernel<<<1024, 128>>>(cb, out);
}

// round 11
// speedup vs baseline: 1.4747x; 1.2680x over previous
#include <cuda_runtime.h>
#include <cstdint>

// Problem constants
#define B_    32
#define C_    64
#define HW_   1024
#define N_    32768         // B*H*W
#define K_    1024
#define TMV   64            // points per task
#define NTC   128           // codes per task (slice)
#define NTASK 4096          // 512 point-tiles x 8 slices
#define NBLK  296           // persistent blocks (2 per SM)

// ---------------------------------------------------------------------------
// Scratch (no cudaMalloc allowed)
// ---------------------------------------------------------------------------
// Negated codebook, transposed + bank-swizzled per slice:
//   g_csw[s*8192 + c*128 + jj*64 + tx*4 + r] = -cb[(s*128 + tx*8 + jj*4 + r)*64 + c]
__device__ float g_csw[K_ * C_];
__device__ float g_hn[K_];                    // 0.5*||c_k||^2
__device__ unsigned long long g_best[N_];     // packed (monotone dist | idx)

// Monotone float->uint mapping (preserves total order incl. negatives)
__device__ __forceinline__ unsigned int fkey(float f) {
    unsigned int u = __float_as_uint(f);
    return (u & 0x80000000u) ? ~u : (u | 0x80000000u);
}

__device__ __forceinline__ unsigned int smem_u32(const void* p) {
    unsigned int a;
    asm("{ .reg .u64 t; cvta.to.shared.u64 t, %1; cvt.u32.u64 %0, t; }"
        : "=r"(a) : "l"(p));
    return a;
}

__device__ __forceinline__ void cp_async16(unsigned int dst, const void* src) {
    asm volatile("cp.async.cg.shared.global [%0], [%1], 16;"
                 :: "r"(dst), "l"(src) : "memory");
}

// ---------------------------------------------------------------------------
// Prep: negated/transposed/swizzled codebook + half norms + g_best init.
// 8 blocks x 128 threads (one thread per code row).
// ---------------------------------------------------------------------------
__global__ __launch_bounds__(128)
void prep_cb_kernel(const float* __restrict__ cb) {
    const int k  = blockIdx.x * 128 + threadIdx.x;   // 0..1023
    const int gt = k;
    const int s  = k >> 7;
    const int kk = k & 127;
    const int tx = kk >> 3;
    const int jj = (kk >> 2) & 1;
    const int r  = kk & 3;
    float* dst = &g_csw[s * 8192 + jj * 64 + tx * 4 + r];

    float sum = 0.f;
#pragma unroll
    for (int c0 = 0; c0 < C_; c0 += 8) {
        float4 va = *(const float4*)&cb[(size_t)k * C_ + c0];
        float4 vb = *(const float4*)&cb[(size_t)k * C_ + c0 + 4];
        float xv[8] = {va.x, va.y, va.z, va.w, vb.x, vb.y, vb.z, vb.w};
#pragma unroll
        for (int j = 0; j < 8; ++j) {
            float x = xv[j];
            sum += x * x;
            dst[(c0 + j) * 128] = -x;
        }
    }
    g_hn[k] = 0.5f * sum;

    for (int i = gt; i < N_; i += 1024)
        g_best[i] = 0xFFFFFFFFFFFFFFFFull;
}

// ---------------------------------------------------------------------------
// Persistent vq kernel. 296 blocks x 256 threads, 2 CTAs/SM.
// Each block loops over tasks (b, b+296, ...); double-buffered cp.async
// staging overlapped with FFMA2 compute.
// Buffer layout: xs [64c][64m] fp32 @0 (16KB), cs swizzled @16384 (32KB),
//                hn @49152 (512B). BUF_SZ=49664, 2 buffers = 99328 B.
// ---------------------------------------------------------------------------
#define XS_OFF 0
#define CS_OFF 16384
#define HN_OFF 49152
#define BUF_SZ 49664
#define SMEM_SZ (2 * BUF_SZ)

__device__ __forceinline__ void stage_task(unsigned int sb, const float* __restrict__ z,
                                           int task, int tid) {
    const int p   = task >> 3;          // point tile
    const int s   = task & 7;           // code slice
    const int n0  = p * TMV;
    const int b   = n0 >> 10;
    const int hw0 = n0 & 1023;
    const char* zsrc = (const char*)(z + (size_t)b * C_ * HW_ + hw0);
    const char* csrc = (const char*)(g_csw + s * 8192);
    const char* hsrc = (const char*)(g_hn + s * NTC);

    // x tile: 1024 16B chunks ([c][64 floats] rows of 256B)
#pragma unroll
    for (int i = 0; i < 4; ++i) {
        int idx = tid + i * 256;
        int c   = idx >> 4;
        int o   = (idx & 15) * 16;
        cp_async16(sb + XS_OFF + idx * 16, zsrc + (size_t)c * HW_ * 4 + o);
    }
    // c tile: 2048 16B chunks (contiguous 32KB slice)
#pragma unroll
    for (int i = 0; i < 8; ++i) {
        int idx = tid + i * 256;
        cp_async16(sb + CS_OFF + idx * 16, csrc + idx * 16);
    }
    if (tid < 32) cp_async16(sb + HN_OFF + tid * 16, hsrc + tid * 16);
    asm volatile("cp.async.commit_group;" ::: "memory");
}

__global__ __launch_bounds__(256, 2)
void vq_kernel(const float* __restrict__ z) {
    extern __shared__ char smem[];
    const unsigned int sb0 = smem_u32(smem);
    const int tid = threadIdx.x;
    const int tx  = tid & 15;           // code-column group (8 cols)
    const int ty  = tid >> 4;           // point-row group (4 rows)
    const int lane = tid & 31;

    int t   = blockIdx.x;
    int cur = 0;
    if (t < NTASK) stage_task(sb0, z, t, tid);

    while (t < NTASK) {
        char* buf = smem + cur * BUF_SZ;
        const int tnext = t + NBLK;
        if (tnext < NTASK) stage_task(sb0 + (cur ^ 1) * BUF_SZ, z, tnext, tid);

        if (tnext < NTASK)
            asm volatile("cp.async.wait_group 1;" ::: "memory");
        else
            asm volatile("cp.async.wait_group 0;" ::: "memory");
        __syncthreads();

        // ---- compute task t from buf ----
        const float* xs = (const float*)(buf + XS_OFF);
        const float* cs = (const float*)(buf + CS_OFF);
        const float* hn = (const float*)(buf + HN_OFF);

        unsigned long long acc[4][4];
        {
            ulonglong2 h01 = *(const ulonglong2*)&hn[tx * 8];
            ulonglong2 h23 = *(const ulonglong2*)&hn[tx * 8 + 4];
            unsigned long long hh[4] = {h01.x, h01.y, h23.x, h23.y};
#pragma unroll
            for (int i = 0; i < 4; ++i)
#pragma unroll
                for (int j = 0; j < 4; ++j) acc[i][j] = hh[j];
        }

#pragma unroll 4
        for (int c = 0; c < C_; ++c) {
            float4 xv = *(const float4*)&xs[c * 64 + ty * 4];
            ulonglong2 ca = *(const ulonglong2*)&cs[c * 128 + tx * 4];
            ulonglong2 cbp = *(const ulonglong2*)&cs[c * 128 + 64 + tx * 4];
            unsigned long long cc[4] = {ca.x, ca.y, cbp.x, cbp.y};
            float xr[4] = {xv.x, xv.y, xv.z, xv.w};
#pragma unroll
            for (int i = 0; i < 4; ++i) {
                unsigned long long xd;
                asm("mov.b64 %0, {%1, %1};"
                    : "=l"(xd) : "r"(__float_as_uint(xr[i])));
#pragma unroll
                for (int j = 0; j < 4; ++j)
                    asm("fma.rn.f32x2 %0, %1, %2, %0;"
                        : "+l"(acc[i][j]) : "l"(xd), "l"(cc[j]));
            }
        }

        // ---- per-thread argmin over its 8 cols (ascending => first-wins) ----
        const int p  = t >> 3;
        const int s  = t & 7;
        const int n0 = p * TMV;
        float bv[4];
        int   bi[4];
#pragma unroll
        for (int i = 0; i < 4; ++i) { bv[i] = 3.4e38f; bi[i] = 0x7fffffff; }
#pragma unroll
        for (int i = 0; i < 4; ++i) {
#pragma unroll
            for (int j = 0; j < 4; ++j) {
                float vlo = __uint_as_float((unsigned int)acc[i][j]);
                float vhi = __uint_as_float((unsigned int)(acc[i][j] >> 32));
                int col = tx * 8 + j * 2;
                if (vlo < bv[i]) { bv[i] = vlo; bi[i] = col; }
                if (vhi < bv[i]) { bv[i] = vhi; bi[i] = col + 1; }
            }
        }
        // reduce across 16 tx-threads sharing the 4 rows
#pragma unroll
        for (int i = 0; i < 4; ++i) {
#pragma unroll
            for (int off = 8; off > 0; off >>= 1) {
                float ov = __shfl_xor_sync(0xffffffffu, bv[i], off, 16);
                int   oi = __shfl_xor_sync(0xffffffffu, bi[i], off, 16);
                if (ov < bv[i] || (ov == bv[i] && oi < bi[i])) { bv[i] = ov; bi[i] = oi; }
            }
        }
        if (tx == 0) {
#pragma unroll
            for (int i = 0; i < 4; ++i) {
                unsigned long long key =
                    ((unsigned long long)fkey(bv[i]) << 32)
                    | (unsigned int)(s * NTC + bi[i]);
                atomicMin(&g_best[n0 + ty * 4 + i], key);
            }
        }
        (void)lane;
        __syncthreads();                 // buf free before next prefetch reuses it

        t = tnext;
        cur ^= 1;
    }
}

// ---------------------------------------------------------------------------
// Finalize: 1024 blocks x 128 threads, 32 points each. float4 output stores.
// ---------------------------------------------------------------------------
#define TF 32
__global__ __launch_bounds__(128)
void finalize_kernel(const float* __restrict__ cb, float* __restrict__ out) {
    __shared__ float scodes[TF * 65];
    __shared__ int   sidx[TF];

    const int tid = threadIdx.x;
    const int n0  = blockIdx.x * TF;
    const int b   = n0 / HW_;
    const int hw0 = n0 % HW_;

    if (tid < TF) {
        unsigned long long key = g_best[n0 + tid];
        int idx = (int)(unsigned int)(key & 0xFFFFFFFFull);
        sidx[tid] = idx;
        out[(size_t)B_ * C_ * HW_ + n0 + tid] = (float)idx;
    }
    __syncthreads();

    {
#pragma unroll
        for (int i = 0; i < 4; ++i) {
            int idx = tid + i * 128;           // 0..511 float4s
            int m   = idx >> 4;
            int c4  = (idx & 15) * 4;
            float4 v = *(const float4*)&cb[sidx[m] * C_ + c4];
            scodes[m * 65 + c4 + 0] = v.x;
            scodes[m * 65 + c4 + 1] = v.y;
            scodes[m * 65 + c4 + 2] = v.z;
            scodes[m * 65 + c4 + 3] = v.w;
        }
    }
    __syncthreads();

    {
        int m4    = (tid & 7) * 4;             // 0..28
        int cbase = tid >> 3;                  // 0..15
        float* ob = out + (size_t)b * C_ * HW_ + hw0;
#pragma unroll
        for (int j = 0; j < 4; ++j) {
            int c = cbase + j * 16;
            float4 w;
            w.x = scodes[(m4 + 0) * 65 + c];
            w.y = scodes[(m4 + 1) * 65 + c];
            w.z = scodes[(m4 + 2) * 65 + c];
            w.w = scodes[(m4 + 3) * 65 + c];
            *(float4*)&ob[c * HW_ + m4] = w;
        }
    }
}

// ---------------------------------------------------------------------------
extern "C" void kernel_launch(void* const* d_in, const int* in_sizes, int n_in,
                              void* d_out, int out_size) {
    const float* z  = (const float*)d_in[0];
    const float* cb = (const float*)d_in[1];
    float* out = (float*)d_out;
    (void)in_sizes; (void)n_in; (void)out_size;

    cudaFuncSetAttribute(vq_kernel,
                         cudaFuncAttributeMaxDynamicSharedMemorySize, SMEM_SZ);

    prep_cb_kernel<<<8, 128>>>(cb);
    vq_kernel<<<NBLK, 256, SMEM_SZ>>>(z);
    finalize_kernel<<<1024, 128>>>(cb, out);
}

// round 12
// speedup vs baseline: 1.7496x; 1.1864x over previous
#include <cuda_runtime.h>
#include <cuda_bf16.h>
#include <cstdint>

// Problem constants
#define B_    32
#define C_    64
#define HW_   1024
#define N_    32768         // B*H*W
#define K_    1024
#define TMV   64            // points per task
#define NTC   128           // codes per task (slice)
#define NTASK 4096          // 512 point-tiles x 8 slices
#define NBLK  296           // persistent blocks (2 per SM)

// ---------------------------------------------------------------------------
// Scratch (no cudaMalloc allowed)
// ---------------------------------------------------------------------------
__device__ __align__(16) unsigned short g_c1[K_ * C_];  // bf16 codebook [k][c]
__device__ float g_hn[K_];                    // 0.5*||c_k||^2
__device__ unsigned long long g_best[N_];     // packed (monotone dist | idx)

// Monotone float<->uint order-preserving mapping
__device__ __forceinline__ unsigned int fkey(float f) {
    unsigned int u = __float_as_uint(f);
    return (u & 0x80000000u) ? ~u : (u | 0x80000000u);
}
__device__ __forceinline__ float fkey_dec(unsigned int k) {
    return (k & 0x80000000u) ? __uint_as_float(k & 0x7fffffffu)
                             : __uint_as_float(~k);
}

__device__ __forceinline__ unsigned int smem_u32(const void* p) {
    unsigned int a;
    asm("{ .reg .u64 t; cvta.to.shared.u64 t, %1; cvt.u32.u64 %0, t; }"
        : "=r"(a) : "l"(p));
    return a;
}

__device__ __forceinline__ void cp_async16(unsigned int dst, const void* src) {
    asm volatile("cp.async.cg.shared.global [%0], [%1], 16;"
                 :: "r"(dst), "l"(src) : "memory");
}

// ---------------------------------------------------------------------------
// Prep: bf16 codebook + half norms + g_best init. 128 blocks x 256 threads.
// ---------------------------------------------------------------------------
__global__ __launch_bounds__(256)
void prep_cb_kernel(const float* __restrict__ cb) {
    const int gid = blockIdx.x * 256 + threadIdx.x;   // 0..32767
    if (gid < K_) {
        const int k = gid;
        const size_t krow = (size_t)k * C_;
        float s = 0.f;
#pragma unroll
        for (int c0 = 0; c0 < C_; c0 += 8) {
            float4 va = *(const float4*)&cb[krow + c0];
            float4 vb = *(const float4*)&cb[krow + c0 + 4];
            float xv[8] = {va.x, va.y, va.z, va.w, vb.x, vb.y, vb.z, vb.w};
            uint4 p;
            unsigned short* sp = (unsigned short*)&p;
#pragma unroll
            for (int j = 0; j < 8; ++j) {
                float x = xv[j];
                s += x * x;
                sp[j] = __bfloat16_as_ushort(__float2bfloat16(x));
            }
            *(uint4*)&g_c1[krow + c0] = p;
        }
        g_hn[k] = 0.5f * s;
    }
    g_best[gid] = 0xFFFFFFFFFFFFFFFFull;
}

// ---------------------------------------------------------------------------
// Persistent vq kernel. 296 blocks x 256 threads, 2 CTAs/SM.
// Per task: cp.async stage (fp32 x [c][m] 16KB, bf16 codes swizzled 16KB, hn)
// -> in-kernel convert to bf16 A tile -> HMMA filter -> branchless hitmask
// scan -> smem queue -> uniform exact fp32 verify -> atomicMin(g_best).
// ---------------------------------------------------------------------------
#define XF_OFF   0            // fp32 x [64 c][64 m] : 16384
#define XB_OFF   16384        // bf16 x [64 m][128B] swizzled : 8192
#define CB_OFF   24576        // bf16 c [128 n][128B] swizzled : 16384
#define HN_OFF   40960        // 512
#define BUF_SZ   41472
#define SRM_OFF  (2 * BUF_SZ)          // 64 u32 row-min : 256
#define SS_OFF   (2 * BUF_SZ + 256)    // 64 f32 sum|x| : 256
#define QC_OFF   (2 * BUF_SZ + 512)    // 16
#define OVF_OFF  (2 * BUF_SZ + 528)    // 16
#define QU_OFF   (2 * BUF_SZ + 544)
#define QCAP     1024
#define SMEM_SZ  (QU_OFF + QCAP * 4)   // 87584

__device__ __forceinline__ void stage_task(unsigned int sb, const float* __restrict__ z,
                                           int task, int tid) {
    const int p   = task >> 3;
    const int s   = task & 7;
    const int n0  = p * TMV;
    const int b   = n0 >> 10;
    const int hw0 = n0 & 1023;
    const char* zsrc = (const char*)(z + (size_t)b * C_ * HW_ + hw0);
    const char* csrc = (const char*)(g_c1 + (size_t)s * NTC * C_);
    const char* hsrc = (const char*)(g_hn + s * NTC);

    // fp32 x tile: [c][64 floats] rows of 256B -> 1024 16B chunks
#pragma unroll
    for (int i = 0; i < 4; ++i) {
        int idx = tid + i * 256;
        int c   = idx >> 4;
        int o   = (idx & 15) * 16;
        cp_async16(sb + XF_OFF + idx * 16, zsrc + (size_t)c * HW_ * 4 + o);
    }
    // bf16 code tile: 128 rows x 128B, swizzled 16B chunks
#pragma unroll
    for (int i = 0; i < 4; ++i) {
        int idx = tid + i * 256;
        int row = idx >> 3;
        int chk = idx & 7;
        cp_async16(sb + CB_OFF + row * 128 + ((chk ^ (row & 7)) * 16),
                   csrc + idx * 16);
    }
    if (tid < 32) cp_async16(sb + HN_OFF + tid * 16, hsrc + tid * 16);
    asm volatile("cp.async.commit_group;" ::: "memory");
}

__global__ __launch_bounds__(256, 2)
void vq_kernel(const float* __restrict__ z, const float* __restrict__ cb) {
    extern __shared__ char smem[];
    const unsigned int sb0 = smem_u32(smem);
    unsigned int* srm = (unsigned int*)(smem + SRM_OFF);
    float*        sS  = (float*)(smem + SS_OFF);
    int*          qc  = (int*)(smem + QC_OFF);
    unsigned int* ovf = (unsigned int*)(smem + OVF_OFF);
    int*          qu  = (int*)(smem + QU_OFF);

    const int tid  = threadIdx.x;
    const int wid  = tid >> 5;
    const int lane = tid & 31;

    int t   = blockIdx.x;
    int cur = 0;
    if (t < NTASK) stage_task(sb0, z, t, tid);

    while (t < NTASK) {
        char* buf = smem + cur * BUF_SZ;
        const unsigned int sbuf = sb0 + cur * BUF_SZ;
        const int tnext = t + NBLK;
        if (tnext < NTASK) stage_task(sb0 + (cur ^ 1) * BUF_SZ, z, tnext, tid);

        if (tnext < NTASK)
            asm volatile("cp.async.wait_group 1;" ::: "memory");
        else
            asm volatile("cp.async.wait_group 0;" ::: "memory");
        __syncthreads();

        const float* xf = (const float*)(buf + XF_OFF);
        const float* hn = (const float*)(buf + HN_OFF);

        // ---- Phase A: convert fp32 [c][m] -> bf16 [m][c] (swizzled) + S ----
        {
            const int m  = tid >> 2;
            const int c0 = (tid & 3) * 16;
            float v[16];
            float S = 0.f;
#pragma unroll
            for (int j = 0; j < 16; ++j) {
                v[j] = xf[(c0 + j) * 64 + m];
                S += fabsf(v[j]);
            }
            unsigned int pk[8];
#pragma unroll
            for (int j = 0; j < 8; ++j)
                asm("cvt.rn.bf16x2.f32 %0, %1, %2;"
                    : "=r"(pk[j]) : "f"(v[j * 2 + 1]), "f"(v[j * 2]));
            const int cb0 = 2 * (tid & 3);          // first 16B chunk index
#pragma unroll
            for (int g = 0; g < 2; ++g) {
                unsigned int addr = sbuf + XB_OFF + m * 128
                                  + (((cb0 + g) ^ (m & 7)) * 16);
                asm volatile("st.shared.v4.b32 [%0], {%1,%2,%3,%4};"
                             :: "r"(addr), "r"(pk[g*4+0]), "r"(pk[g*4+1]),
                                "r"(pk[g*4+2]), "r"(pk[g*4+3]) : "memory");
            }
            S += __shfl_xor_sync(0xffffffffu, S, 1, 4);
            S += __shfl_xor_sync(0xffffffffu, S, 2, 4);
            if ((tid & 3) == 0) sS[m] = S;
            if (tid < 64) srm[tid] = 0xFFFFFFFFu;
            if (tid == 0) *qc = 0;
            if (tid < 2)  ovf[tid] = 0u;
        }
        __syncthreads();

        // ---- Phase B: bf16 HMMA filter (64x128x64) ----
        const int mrow0 = (wid & 3) * 16;
        const int ncol0 = (wid >> 2) * 64;
        const int q  = lane >> 3;
        const int rl = lane & 7;
        const int arow = (q & 1) * 8 + rl;
        const int akh  = q >> 1;
        const int brow = (q >> 1) * 8 + rl;
        const int bkh  = q & 1;

        float acc[8][4];
#pragma unroll
        for (int nt = 0; nt < 8; ++nt)
#pragma unroll
            for (int e = 0; e < 4; ++e) acc[nt][e] = 0.f;

#pragma unroll
        for (int kc = 0; kc < 4; ++kc) {
            unsigned int af[4];
            {
                int row = mrow0 + arow;
                unsigned int addr = sbuf + XB_OFF + row * 128
                                  + (((kc * 2 + akh) ^ (row & 7)) * 16);
                asm volatile("ldmatrix.sync.aligned.m8n8.x4.shared.b16 "
                             "{%0,%1,%2,%3}, [%4];"
                             : "=r"(af[0]), "=r"(af[1]), "=r"(af[2]), "=r"(af[3])
                             : "r"(addr));
            }
            unsigned int bf[4][4];
#pragma unroll
            for (int nt2 = 0; nt2 < 4; ++nt2) {
                int row = ncol0 + nt2 * 16 + brow;
                unsigned int addr = sbuf + CB_OFF + row * 128
                                  + (((kc * 2 + bkh) ^ (row & 7)) * 16);
                asm volatile("ldmatrix.sync.aligned.m8n8.x4.shared.b16 "
                             "{%0,%1,%2,%3}, [%4];"
                             : "=r"(bf[nt2][0]), "=r"(bf[nt2][1]),
                               "=r"(bf[nt2][2]), "=r"(bf[nt2][3])
                             : "r"(addr));
            }
#pragma unroll
            for (int nt = 0; nt < 8; ++nt) {
                int nt2 = nt >> 1, hi = nt & 1;
                asm volatile(
                    "mma.sync.aligned.m16n8k16.row.col.f32.bf16.bf16.f32 "
                    "{%0,%1,%2,%3}, {%4,%5,%6,%7}, {%8,%9}, {%0,%1,%2,%3};"
                    : "+f"(acc[nt][0]), "+f"(acc[nt][1]),
                      "+f"(acc[nt][2]), "+f"(acc[nt][3])
                    : "r"(af[0]), "r"(af[1]), "r"(af[2]), "r"(af[3]),
                      "r"(bf[nt2][hi * 2]), "r"(bf[nt2][hi * 2 + 1]));
            }
        }

        // ---- Phase C: per-row approx min -> smem (fkey atomicMin) ----
        const int r0 = mrow0 + (lane >> 2);
        const int r1 = r0 + 8;
        {
            float bv0 = 3.4e38f, bv1 = 3.4e38f;
#pragma unroll
            for (int nt = 0; nt < 8; ++nt) {
                int colb = ncol0 + nt * 8 + (lane & 3) * 2;
                float h0 = hn[colb], h1 = hn[colb + 1];
                bv0 = fminf(bv0, fminf(h0 - acc[nt][0], h1 - acc[nt][1]));
                bv1 = fminf(bv1, fminf(h0 - acc[nt][2], h1 - acc[nt][3]));
            }
            bv0 = fminf(bv0, __shfl_xor_sync(0xffffffffu, bv0, 1));
            bv0 = fminf(bv0, __shfl_xor_sync(0xffffffffu, bv0, 2));
            bv1 = fminf(bv1, __shfl_xor_sync(0xffffffffu, bv1, 1));
            bv1 = fminf(bv1, __shfl_xor_sync(0xffffffffu, bv1, 2));
            if ((lane & 3) == 0) {
                atomicMin(&srm[r0], fkey(bv0));
                atomicMin(&srm[r1], fkey(bv1));
            }
        }
        __syncthreads();

        // ---- Phase D: branchless hitmask scan -> compact queue ----
        {
            const float T0 = fkey_dec(srm[r0]) + sS[r0] * 0.0158f + 0.002f;
            const float T1 = fkey_dec(srm[r1]) + sS[r1] * 0.0158f + 0.002f;
            unsigned int mask = 0;
#pragma unroll
            for (int nt = 0; nt < 8; ++nt) {
                int colb = ncol0 + nt * 8 + (lane & 3) * 2;
                float h0 = hn[colb], h1 = hn[colb + 1];
                mask |= (unsigned int)((h0 - acc[nt][0]) <= T0) << (nt * 4 + 0);
                mask |= (unsigned int)((h1 - acc[nt][1]) <= T0) << (nt * 4 + 1);
                mask |= (unsigned int)((h0 - acc[nt][2]) <= T1) << (nt * 4 + 2);
                mask |= (unsigned int)((h1 - acc[nt][3]) <= T1) << (nt * 4 + 3);
            }
            int cnt = __popc(mask);
            int incl = cnt;
#pragma unroll
            for (int off = 1; off < 32; off <<= 1) {
                int tmp = __shfl_up_sync(0xffffffffu, incl, off);
                if (lane >= off) incl += tmp;
            }
            int total = __shfl_sync(0xffffffffu, incl, 31);
            int base = 0;
            if (lane == 31 && total > 0) base = atomicAdd(qc, total);
            base = __shfl_sync(0xffffffffu, base, 31);
            int pos = base + incl - cnt;
            while (mask) {
                int bgd = __ffs(mask) - 1;
                mask &= mask - 1;
                int nt = bgd >> 2, j = bgd & 3;
                int row = (j < 2) ? r0 : r1;
                int col = ncol0 + nt * 8 + (lane & 3) * 2 + (j & 1);
                if (pos < QCAP) qu[pos] = (row << 8) | col;
                else atomicOr(&ovf[row >> 5], 1u << (row & 31));
                ++pos;
            }
        }
        __syncthreads();

        // ---- Phase E: uniform exact fp32 verify ----
        const int p  = t >> 3;
        const int s  = t & 7;
        const int n0 = p * TMV;
        const size_t cbbase = (size_t)s * NTC * C_;
        int qn = *qc;
        if (qn > QCAP) qn = QCAP;
        for (int i = tid; i < qn; i += 256) {
            int e   = qu[i];
            int row = e >> 8;
            int col = e & 255;
            const float4* cr = (const float4*)&cb[cbbase + (size_t)col * C_];
            float sv = hn[col];
#pragma unroll
            for (int c4 = 0; c4 < 16; ++c4) {
                float4 cv = cr[c4];
                sv = fmaf(-xf[(c4 * 4 + 0) * 64 + row], cv.x, sv);
                sv = fmaf(-xf[(c4 * 4 + 1) * 64 + row], cv.y, sv);
                sv = fmaf(-xf[(c4 * 4 + 2) * 64 + row], cv.z, sv);
                sv = fmaf(-xf[(c4 * 4 + 3) * 64 + row], cv.w, sv);
            }
            unsigned long long key =
                ((unsigned long long)fkey(sv) << 32)
                | (unsigned int)(s * NTC + col);
            atomicMin(&g_best[n0 + row], key);
        }

        // ---- overflow rows (queue full): exact rescan, ~never taken ----
        if (ovf[0] | ovf[1]) {
            for (int r = 0; r < TMV; ++r) {
                if (!(ovf[r >> 5] & (1u << (r & 31)))) continue;
                if (tid < NTC) {
                    int col = tid;
                    const float4* cr = (const float4*)&cb[cbbase + (size_t)col * C_];
                    float sv = hn[col];
#pragma unroll
                    for (int c4 = 0; c4 < 16; ++c4) {
                        float4 cv = cr[c4];
                        sv = fmaf(-xf[(c4 * 4 + 0) * 64 + r], cv.x, sv);
                        sv = fmaf(-xf[(c4 * 4 + 1) * 64 + r], cv.y, sv);
                        sv = fmaf(-xf[(c4 * 4 + 2) * 64 + r], cv.z, sv);
                        sv = fmaf(-xf[(c4 * 4 + 3) * 64 + r], cv.w, sv);
                    }
                    unsigned long long key =
                        ((unsigned long long)fkey(sv) << 32)
                        | (unsigned int)(s * NTC + col);
                    atomicMin(&g_best[n0 + r], key);
                }
            }
        }
        __syncthreads();

        t = tnext;
        cur ^= 1;
    }
}

// ---------------------------------------------------------------------------
// Finalize: 1024 blocks x 128 threads, 32 points each. float4 output stores.
// ---------------------------------------------------------------------------
#define TF 32
__global__ __launch_bounds__(128)
void finalize_kernel(const float* __restrict__ cb, float* __restrict__ out) {
    __shared__ float scodes[TF * 65];
    __shared__ int   sidx[TF];

    const int tid = threadIdx.x;
    const int n0  = blockIdx.x * TF;
    const int b   = n0 / HW_;
    const int hw0 = n0 % HW_;

    if (tid < TF) {
        unsigned long long key = g_best[n0 + tid];
        int idx = (int)(unsigned int)(key & 0xFFFFFFFFull);
        sidx[tid] = idx;
        out[(size_t)B_ * C_ * HW_ + n0 + tid] = (float)idx;
    }
    __syncthreads();

    {
#pragma unroll
        for (int i = 0; i < 4; ++i) {
            int idx = tid + i * 128;           // 0..511 float4s
            int m   = idx >> 4;
            int c4  = (idx & 15) * 4;
            float4 v = *(const float4*)&cb[sidx[m] * C_ + c4];
            scodes[m * 65 + c4 + 0] = v.x;
            scodes[m * 65 + c4 + 1] = v.y;
            scodes[m * 65 + c4 + 2] = v.z;
            scodes[m * 65 + c4 + 3] = v.w;
        }
    }
    __syncthreads();

    {
        int m4    = (tid & 7) * 4;             // 0..28
        int cbase = tid >> 3;                  // 0..15
        float* ob = out + (size_t)b * C_ * HW_ + hw0;
#pragma unroll
        for (int j = 0; j < 4; ++j) {
            int c = cbase + j * 16;
            float4 w;
            w.x = scodes[(m4 + 0) * 65 + c];
            w.y = scodes[(m4 + 1) * 65 + c];
            w.z = scodes[(m4 + 2) * 65 + c];
            w.w = scodes[(m4 + 3) * 65 + c];
            *(float4*)&ob[c * HW_ + m4] = w;
        }
    }
}

// ---------------------------------------------------------------------------
extern "C" void kernel_launch(void* const* d_in, const int* in_sizes, int n_in,
                              void* d_out, int out_size) {
    const float* z  = (const float*)d_in[0];
    const float* cb = (const float*)d_in[1];
    float* out = (float*)d_out;
    (void)in_sizes; (void)n_in; (void)out_size;

    cudaFuncSetAttribute(vq_kernel,
                         cudaFuncAttributeMaxDynamicSharedMemorySize, SMEM_SZ);

    prep_cb_kernel<<<128, 256>>>(cb);
    vq_kernel<<<NBLK, 256, SMEM_SZ>>>(z, cb);
    finalize_kernel<<<1024, 128>>>(cb, out);
}